// round 7
// baseline (speedup 1.0000x reference)
#include <cuda_runtime.h>
#include <math.h>
#include <stdint.h>

#define MAX_E     4194304
#define MAX_NOUT  524288
#define CCH       64            // channels
#define CV4       16            // float4 per row

// -------- device scratch (no dynamic allocation allowed) --------
// Arrays accessed through int4* views MUST be 16B-aligned (err715 otherwise).
__device__ __align__(16) int g_vsrc[MAX_E];      // valid ? src : -1
__device__ __align__(16) int g_bins[MAX_E];
__device__ int  g_counts [MAX_NOUT];
__device__ int  g_cursor [MAX_NOUT];
__device__ int2 g_seg    [MAX_NOUT];             // {offset, count}
__device__ int  g_total;                         // atomic base for scan blocks

// -------- kernel 1: zero counters --------
__global__ void k_zero(int n_out) {
    int i = blockIdx.x * blockDim.x + threadIdx.x;
    if (i < n_out) g_counts[i] = 0;
    if (i == 0) g_total = 0;
}

// -------- kernel 2: histogram + validity fusion (4 edges/thread, int4) -----
__global__ void k_count_v4(const int4* __restrict__ src4,
                           const int4* __restrict__ nt4,
                           int E4) {
    int t = blockIdx.x * blockDim.x + threadIdx.x;
    if (t >= E4) return;
    int4 n0 = __ldg(&nt4[3 * t]);
    int4 n1 = __ldg(&nt4[3 * t + 1]);
    int4 n2 = __ldg(&nt4[3 * t + 2]);
    int4 s  = __ldg(&src4[t]);

    int v0 = (n0.x >= 0 && n0.y >= 0 && n0.z >= 0) ? s.x : -1;
    int v1 = (n0.w >= 0 && n1.x >= 0 && n1.y >= 0) ? s.y : -1;
    int v2 = (n1.z >= 0 && n1.w >= 0 && n2.x >= 0) ? s.z : -1;
    int v3 = (n2.y >= 0 && n2.z >= 0 && n2.w >= 0) ? s.w : -1;

    ((int4*)g_vsrc)[t] = make_int4(v0, v1, v2, v3);
    if ((unsigned)v0 < (unsigned)MAX_NOUT) atomicAdd(&g_counts[v0], 1);
    if ((unsigned)v1 < (unsigned)MAX_NOUT) atomicAdd(&g_counts[v1], 1);
    if ((unsigned)v2 < (unsigned)MAX_NOUT) atomicAdd(&g_counts[v2], 1);
    if ((unsigned)v3 < (unsigned)MAX_NOUT) atomicAdd(&g_counts[v3], 1);
}

// scalar fallback (odd shapes)
__global__ void k_count_s(const int* __restrict__ src_ids,
                          const int* __restrict__ ntypes,
                          int E, int NT) {
    int e = blockIdx.x * blockDim.x + threadIdx.x;
    if (e >= E) return;
    const int* nt = ntypes + (size_t)e * NT;
    bool valid = true;
    for (int j = 0; j < NT; j++) valid &= (nt[j] >= 0);
    int s = src_ids[e];
    int v = (valid && (unsigned)s < (unsigned)MAX_NOUT) ? s : -1;
    g_vsrc[e] = v;
    if (v >= 0) atomicAdd(&g_counts[v], 1);
}

// -------- kernel 3: block scan + atomic base. Offsets need not be globally
// ordered: any disjoint partition of bins is valid, max is order-independent.
__global__ void k_scan_atomic(int n) {
    __shared__ int sh[256];
    __shared__ int sh_base;
    int tid  = threadIdx.x;
    int base = blockIdx.x * 4096 + tid * 16;
    int local[16];
    int cval[16];
    int sum = 0;
    #pragma unroll
    for (int i = 0; i < 16; i++) {
        local[i] = sum;
        int idx = base + i;
        cval[i] = (idx < n) ? g_counts[idx] : 0;
        sum += cval[i];
    }
    sh[tid] = sum;
    __syncthreads();
    for (int off = 1; off < 256; off <<= 1) {
        int v = (tid >= off) ? sh[tid - off] : 0;
        __syncthreads();
        sh[tid] += v;
        __syncthreads();
    }
    if (tid == 255) sh_base = atomicAdd(&g_total, sh[255]);
    __syncthreads();
    int excl = sh_base + sh[tid] - sum;
    #pragma unroll
    for (int i = 0; i < 16; i++) {
        int idx = base + i;
        if (idx < n) {
            int o = excl + local[i];
            g_seg[idx]    = make_int2(o, cval[i]);
            g_cursor[idx] = o;
        }
    }
}

// -------- kernel 4: scatter edges into CSR bins (4 edges/thread) --------
__global__ void k_scatter_v4(const int4* __restrict__ tgt4, int E4) {
    int t = blockIdx.x * blockDim.x + threadIdx.x;
    if (t >= E4) return;
    int4 v  = ((const int4*)g_vsrc)[t];
    int4 tg = __ldg(&tgt4[t]);
    if (v.x >= 0) { int p = atomicAdd(&g_cursor[v.x], 1); if ((unsigned)p < (unsigned)MAX_E) g_bins[p] = tg.x; }
    if (v.y >= 0) { int p = atomicAdd(&g_cursor[v.y], 1); if ((unsigned)p < (unsigned)MAX_E) g_bins[p] = tg.y; }
    if (v.z >= 0) { int p = atomicAdd(&g_cursor[v.z], 1); if ((unsigned)p < (unsigned)MAX_E) g_bins[p] = tg.z; }
    if (v.w >= 0) { int p = atomicAdd(&g_cursor[v.w], 1); if ((unsigned)p < (unsigned)MAX_E) g_bins[p] = tg.w; }
}

__global__ void k_scatter_s(const int* __restrict__ tgt_ids, int E) {
    int e = blockIdx.x * blockDim.x + threadIdx.x;
    if (e >= E) return;
    int v = g_vsrc[e];
    if (v >= 0) {
        int p = atomicAdd(&g_cursor[v], 1);
        if ((unsigned)p < (unsigned)MAX_E) g_bins[p] = tgt_ids[e];
    }
}

// -------- kernel 5: one warp/segment. Warp-wide bin prefetch + shfl
// broadcast: one coalesced LDG fetches up to 32 edge indices, then every feat
// row load is independent (no per-edge dependent index load).
__global__ void k_pool(const float4* __restrict__ feat4,
                       float4* __restrict__ out4,
                       int n_out) {
    int gw    = (blockIdx.x * blockDim.x + threadIdx.x) >> 5;
    int lane  = threadIdx.x & 31;
    int half  = lane >> 4;        // which edge of the pair
    int qlane = lane & 15;        // float4 index within the 64-ch row
    if (gw >= n_out) return;

    int2 seg  = g_seg[gw];
    int start = seg.x;
    int cnt   = seg.y;

    const float NI = -INFINITY;
    float4 acc = make_float4(NI, NI, NI, NI);

    for (int base = 0; base < cnt; base += 32) {
        int m = cnt - base; if (m > 32) m = 32;
        int bin = 0;
        if (lane < m) bin = __ldg(&g_bins[start + base + lane]);

        int pairs = m >> 1;
        #pragma unroll 4
        for (int j = 0; j < pairs; j++) {
            int t = __shfl_sync(0xffffffffu, bin, 2 * j + half);
            float4 a = __ldg(&feat4[(size_t)t * CV4 + qlane]);
            acc.x = fmaxf(acc.x, a.x);
            acc.y = fmaxf(acc.y, a.y);
            acc.z = fmaxf(acc.z, a.z);
            acc.w = fmaxf(acc.w, a.w);
        }
        if (m & 1) {            // last odd edge: both halves read it (converged)
            int t = __shfl_sync(0xffffffffu, bin, m - 1);
            float4 a = __ldg(&feat4[(size_t)t * CV4 + qlane]);
            acc.x = fmaxf(acc.x, a.x);
            acc.y = fmaxf(acc.y, a.y);
            acc.z = fmaxf(acc.z, a.z);
            acc.w = fmaxf(acc.w, a.w);
        }
    }

    // merge the two half-warp partial maxima
    acc.x = fmaxf(acc.x, __shfl_xor_sync(0xffffffffu, acc.x, 16));
    acc.y = fmaxf(acc.y, __shfl_xor_sync(0xffffffffu, acc.y, 16));
    acc.z = fmaxf(acc.z, __shfl_xor_sync(0xffffffffu, acc.z, 16));
    acc.w = fmaxf(acc.w, __shfl_xor_sync(0xffffffffu, acc.w, 16));

    if (cnt == 0) acc = make_float4(0.0f, 0.0f, 0.0f, 0.0f);
    if (half == 0) out4[(size_t)gw * CV4 + qlane] = acc;
}

// -------- optional tail: tuple's second element (feat_depth+1) --------
__global__ void k_tail(float* __restrict__ out, const int* __restrict__ feat_depth,
                       int begin, int total) {
    int i = begin + blockIdx.x * blockDim.x + threadIdx.x;
    if (i < total) out[i] = (float)(feat_depth[0] + 1);
}

extern "C" void kernel_launch(void* const* d_in, const int* in_sizes, int n_in,
                              void* d_out, int out_size) {
    const float* feat    = (const float*)d_in[0];
    const int*   src_ids = (const int*)  d_in[1];
    const int*   tgt_ids = (const int*)  d_in[2];
    const int*   ntypes  = (const int*)  d_in[3];

    int E  = in_sizes[1];
    int NT = (E > 0) ? in_sizes[3] / E : 3;
    if (E > MAX_E) E = MAX_E;
    if (NT < 1) NT = 1;

    int n_out = out_size / CCH;
    if (n_out > MAX_NOUT) n_out = MAX_NOUT;

    // 1. zero counters
    k_zero<<<(n_out + 255) / 256, 256>>>(n_out);

    // 2. histogram + validity fusion
    bool vec = (NT == 3) && (E % 4 == 0) &&
               ((((uintptr_t)src_ids | (uintptr_t)tgt_ids | (uintptr_t)ntypes) & 15u) == 0);
    if (vec) {
        int E4 = E / 4;
        k_count_v4<<<(E4 + 255) / 256, 256>>>((const int4*)src_ids,
                                              (const int4*)ntypes, E4);
    } else {
        k_count_s<<<(E + 255) / 256, 256>>>(src_ids, ntypes, E, NT);
    }

    // 3. single-kernel scan with atomic block base
    int nb = (n_out + 4095) / 4096;
    k_scan_atomic<<<nb, 256>>>(n_out);

    // 4. scatter into CSR
    if (vec) {
        int E4 = E / 4;
        k_scatter_v4<<<(E4 + 255) / 256, 256>>>((const int4*)tgt_ids, E4);
    } else {
        k_scatter_s<<<(E + 255) / 256, 256>>>(tgt_ids, E);
    }

    // 5. pool: one warp per segment, 8 warps per block
    int threads = 256;
    long long totalThreads = (long long)n_out * 32;
    int blocks = (int)((totalThreads + threads - 1) / threads);
    k_pool<<<blocks, threads>>>((const float4*)feat, (float4*)d_out, n_out);

    // tuple scalar tail (no-op for out_size == n_out*C)
    int main_elems = n_out * CCH;
    if (out_size > main_elems && n_in >= 6) {
        int extra = out_size - main_elems;
        k_tail<<<(extra + 255) / 256, 256>>>((float*)d_out, (const int*)d_in[5],
                                             main_elems, out_size);
    }
}

// round 8
// speedup vs baseline: 1.3622x; 1.3622x over previous
#include <cuda_runtime.h>
#include <math.h>
#include <stdint.h>

#define MAX_E     4194304
#define MAX_NOUT  524288
#define CCH       64            // channels
#define CV4       16            // float4 per row
#define CAP       32            // bin slots per segment (P(deg>32) ~ 1e-16)
#define OVF_CAP   65536

// -------- device scratch (no dynamic allocation allowed) --------
__device__ __align__(16) int g_bins[(size_t)MAX_NOUT * CAP];  // 64 MB
__device__ int  g_cursor[MAX_NOUT];      // per-segment valid-edge count
__device__ int  g_ovf_cnt;
__device__ int2 g_ovf[OVF_CAP];          // {seg, tgt} for theoretical overflow

// -------- kernel 1: zero cursors --------
__global__ void k_zero(int n_out) {
    int i = blockIdx.x * blockDim.x + threadIdx.x;
    if (i < n_out) g_cursor[i] = 0;
    if (i == 0) g_ovf_cnt = 0;
}

// -------- kernel 2: fused validity + direct scatter (4 edges/thread) ------
__device__ __forceinline__ void scatter_one(int s, int tgt) {
    if ((unsigned)s >= (unsigned)MAX_NOUT) return;
    int p = atomicAdd(&g_cursor[s], 1);
    if (p < CAP) {
        g_bins[(size_t)s * CAP + p] = tgt;
    } else {
        int o = atomicAdd(&g_ovf_cnt, 1);
        if (o < OVF_CAP) g_ovf[o] = make_int2(s, tgt);
    }
}

__global__ void k_scatter_v4(const int4* __restrict__ src4,
                             const int4* __restrict__ tgt4,
                             const int4* __restrict__ nt4,
                             int E4) {
    int t = blockIdx.x * blockDim.x + threadIdx.x;
    if (t >= E4) return;
    int4 n0 = __ldg(&nt4[3 * t]);
    int4 n1 = __ldg(&nt4[3 * t + 1]);
    int4 n2 = __ldg(&nt4[3 * t + 2]);
    int4 s  = __ldg(&src4[t]);
    int4 tg = __ldg(&tgt4[t]);

    // edge k's 3 ntypes packed across n0..n2
    bool v0 = (n0.x >= 0) & (n0.y >= 0) & (n0.z >= 0);
    bool v1 = (n0.w >= 0) & (n1.x >= 0) & (n1.y >= 0);
    bool v2 = (n1.z >= 0) & (n1.w >= 0) & (n2.x >= 0);
    bool v3 = (n2.y >= 0) & (n2.z >= 0) & (n2.w >= 0);

    if (v0) scatter_one(s.x, tg.x);
    if (v1) scatter_one(s.y, tg.y);
    if (v2) scatter_one(s.z, tg.z);
    if (v3) scatter_one(s.w, tg.w);
}

// scalar fallback (odd shapes)
__global__ void k_scatter_s(const int* __restrict__ src_ids,
                            const int* __restrict__ tgt_ids,
                            const int* __restrict__ ntypes,
                            int E, int NT) {
    int e = blockIdx.x * blockDim.x + threadIdx.x;
    if (e >= E) return;
    const int* nt = ntypes + (size_t)e * NT;
    bool valid = true;
    for (int j = 0; j < NT; j++) valid &= (nt[j] >= 0);
    if (valid) scatter_one(src_ids[e], tgt_ids[e]);
}

// -------- kernel 3: one warp/segment pool (R5-proven shape) --------
// bins row for a segment is a single 128 B line -> coalesced broadcast reads.
__global__ void k_pool(const float4* __restrict__ feat4,
                       float4* __restrict__ out4,
                       int n_out) {
    int gw    = (blockIdx.x * blockDim.x + threadIdx.x) >> 5;   // warp = segment
    int lane  = threadIdx.x & 31;
    int half  = lane >> 4;        // which edge of the pair
    int qlane = lane & 15;        // float4 index within the 64-ch row
    if (gw >= n_out) return;

    int cnt    = g_cursor[gw];
    int stored = cnt < CAP ? cnt : CAP;   // overflow handled post-pool
    const int* bins = g_bins + (size_t)gw * CAP;

    const float NI = -INFINITY;
    float4 acc = make_float4(NI, NI, NI, NI);

    int i = 0;
    // 4 feat rows in flight per warp (2 per half-warp)
    for (; i + 3 < stored; i += 4) {
        int e0 = __ldg(&bins[i + half]);
        int e1 = __ldg(&bins[i + 2 + half]);
        float4 a = __ldg(&feat4[(size_t)e0 * CV4 + qlane]);
        float4 b = __ldg(&feat4[(size_t)e1 * CV4 + qlane]);
        acc.x = fmaxf(acc.x, fmaxf(a.x, b.x));
        acc.y = fmaxf(acc.y, fmaxf(a.y, b.y));
        acc.z = fmaxf(acc.z, fmaxf(a.z, b.z));
        acc.w = fmaxf(acc.w, fmaxf(a.w, b.w));
    }
    for (; i < stored; i += 2) {
        int e = i + half;
        if (e < stored) {
            int t0 = __ldg(&bins[e]);
            float4 a = __ldg(&feat4[(size_t)t0 * CV4 + qlane]);
            acc.x = fmaxf(acc.x, a.x);
            acc.y = fmaxf(acc.y, a.y);
            acc.z = fmaxf(acc.z, a.z);
            acc.w = fmaxf(acc.w, a.w);
        }
    }

    // merge the two half-warp partial maxima
    acc.x = fmaxf(acc.x, __shfl_xor_sync(0xffffffffu, acc.x, 16));
    acc.y = fmaxf(acc.y, __shfl_xor_sync(0xffffffffu, acc.y, 16));
    acc.z = fmaxf(acc.z, __shfl_xor_sync(0xffffffffu, acc.z, 16));
    acc.w = fmaxf(acc.w, __shfl_xor_sync(0xffffffffu, acc.w, 16));

    if (cnt == 0) acc = make_float4(0.0f, 0.0f, 0.0f, 0.0f);
    if (half == 0) out4[(size_t)gw * CV4 + qlane] = acc;
}

// -------- kernel 4: resolve theoretical overflow (normally 0 entries) ------
__device__ __forceinline__ void atomicMaxFloat(float* addr, float val) {
    int* ia  = (int*)addr;
    int  old = *ia;
    while (__int_as_float(old) < val) {
        int assumed = old;
        old = atomicCAS(ia, assumed, __float_as_int(val));
        if (old == assumed) break;
    }
}

__global__ void k_overflow(const float* __restrict__ feat,
                           float* __restrict__ out, int n_out) {
    int n = g_ovf_cnt;
    if (n > OVF_CAP) n = OVF_CAP;
    // one warp per entry, grid-stride
    int warps = (gridDim.x * blockDim.x) >> 5;
    int w     = (blockIdx.x * blockDim.x + threadIdx.x) >> 5;
    int lane  = threadIdx.x & 31;
    for (int k = w; k < n; k += warps) {
        int2 e = g_ovf[k];
        if ((unsigned)e.x >= (unsigned)n_out) continue;
        const float* row = feat + (size_t)e.y * CCH;
        float*       dst = out  + (size_t)e.x * CCH;
        #pragma unroll
        for (int c = lane; c < CCH; c += 32)
            atomicMaxFloat(&dst[c], row[c]);
    }
}

// -------- optional tail: tuple's second element (feat_depth+1) --------
__global__ void k_tail(float* __restrict__ out, const int* __restrict__ feat_depth,
                       int begin, int total) {
    int i = begin + blockIdx.x * blockDim.x + threadIdx.x;
    if (i < total) out[i] = (float)(feat_depth[0] + 1);
}

extern "C" void kernel_launch(void* const* d_in, const int* in_sizes, int n_in,
                              void* d_out, int out_size) {
    const float* feat    = (const float*)d_in[0];
    const int*   src_ids = (const int*)  d_in[1];
    const int*   tgt_ids = (const int*)  d_in[2];
    const int*   ntypes  = (const int*)  d_in[3];

    int E  = in_sizes[1];
    int NT = (E > 0) ? in_sizes[3] / E : 3;
    if (E > MAX_E) E = MAX_E;
    if (NT < 1) NT = 1;

    int n_out = out_size / CCH;
    if (n_out > MAX_NOUT) n_out = MAX_NOUT;

    // 1. zero cursors
    k_zero<<<(n_out + 255) / 256, 256>>>(n_out);

    // 2. fused validity + direct scatter into fixed-capacity bins
    bool vec = (NT == 3) && (E % 4 == 0) &&
               ((((uintptr_t)src_ids | (uintptr_t)tgt_ids | (uintptr_t)ntypes) & 15u) == 0);
    if (vec) {
        int E4 = E / 4;
        k_scatter_v4<<<(E4 + 255) / 256, 256>>>((const int4*)src_ids,
                                                (const int4*)tgt_ids,
                                                (const int4*)ntypes, E4);
    } else {
        k_scatter_s<<<(E + 255) / 256, 256>>>(src_ids, tgt_ids, ntypes, E, NT);
    }

    // 3. pool: one warp per segment, 8 warps per block
    int threads = 256;
    long long totalThreads = (long long)n_out * 32;
    int blocks = (int)((totalThreads + threads - 1) / threads);
    k_pool<<<blocks, threads>>>((const float4*)feat, (float4*)d_out, n_out);

    // 4. resolve overflow entries (normally none; tiny fixed launch)
    k_overflow<<<16, 256>>>(feat, (float*)d_out, n_out);

    // tuple scalar tail (no-op for out_size == n_out*C)
    int main_elems = n_out * CCH;
    if (out_size > main_elems && n_in >= 6) {
        int extra = out_size - main_elems;
        k_tail<<<(extra + 255) / 256, 256>>>((float*)d_out, (const int*)d_in[5],
                                             main_elems, out_size);
    }
}

// round 9
// speedup vs baseline: 1.5339x; 1.1260x over previous
#include <cuda_runtime.h>
#include <math.h>
#include <stdint.h>

#define MAX_E     4194304
#define MAX_NOUT  524288
#define CCH       64            // channels
#define CV4       16            // float4 per row
#define CAP       32            // bin slots per segment (P(deg>32) ~ 1e-16)
#define OVF_CAP   65536

// -------- device scratch (no dynamic allocation allowed) --------
__device__ __align__(16) int g_bins[(size_t)MAX_NOUT * CAP];  // 64 MB
__device__ int  g_cursor[MAX_NOUT];      // per-segment valid-edge count
__device__ int  g_ovf_cnt;
__device__ int2 g_ovf[OVF_CAP];          // {seg, tgt} for theoretical overflow

// -------- kernel 1: zero cursors --------
__global__ void k_zero(int n_out) {
    int i = blockIdx.x * blockDim.x + threadIdx.x;
    if (i < n_out) g_cursor[i] = 0;
    if (i == 0) g_ovf_cnt = 0;
}

// -------- kernel 2: fused validity + direct scatter (4 edges/thread) ------
__device__ __forceinline__ void scatter_one(int s, int tgt) {
    if ((unsigned)s >= (unsigned)MAX_NOUT) return;
    int p = atomicAdd(&g_cursor[s], 1);
    if (p < CAP) {
        g_bins[(size_t)s * CAP + p] = tgt;
    } else {
        int o = atomicAdd(&g_ovf_cnt, 1);
        if (o < OVF_CAP) g_ovf[o] = make_int2(s, tgt);
    }
}

__global__ void k_scatter_v4(const int4* __restrict__ src4,
                             const int4* __restrict__ tgt4,
                             const int4* __restrict__ nt4,
                             int E4) {
    int t = blockIdx.x * blockDim.x + threadIdx.x;
    if (t >= E4) return;
    int4 n0 = __ldg(&nt4[3 * t]);
    int4 n1 = __ldg(&nt4[3 * t + 1]);
    int4 n2 = __ldg(&nt4[3 * t + 2]);
    int4 s  = __ldg(&src4[t]);
    int4 tg = __ldg(&tgt4[t]);

    bool v0 = (n0.x >= 0) & (n0.y >= 0) & (n0.z >= 0);
    bool v1 = (n0.w >= 0) & (n1.x >= 0) & (n1.y >= 0);
    bool v2 = (n1.z >= 0) & (n1.w >= 0) & (n2.x >= 0);
    bool v3 = (n2.y >= 0) & (n2.z >= 0) & (n2.w >= 0);

    if (v0) scatter_one(s.x, tg.x);
    if (v1) scatter_one(s.y, tg.y);
    if (v2) scatter_one(s.z, tg.z);
    if (v3) scatter_one(s.w, tg.w);
}

// scalar fallback (odd shapes)
__global__ void k_scatter_s(const int* __restrict__ src_ids,
                            const int* __restrict__ tgt_ids,
                            const int* __restrict__ ntypes,
                            int E, int NT) {
    int e = blockIdx.x * blockDim.x + threadIdx.x;
    if (e >= E) return;
    const int* nt = ntypes + (size_t)e * NT;
    bool valid = true;
    for (int j = 0; j < NT; j++) valid &= (nt[j] >= 0);
    if (valid) scatter_one(src_ids[e], tgt_ids[e]);
}

// -------- kernel 3: pool. One segment per HALF-warp (2 segments/warp). ----
// 16 lanes x float4 cover the 64-ch row; 2 rows in flight per half-warp
// (4 per warp). Output written with .cs (evict-first) so the 128 MB of
// write-once data does not evict feat rows from L2 mid-pool.
__global__ void k_pool(const float4* __restrict__ feat4,
                       float4* __restrict__ out4,
                       int n_out) {
    int warp  = (blockIdx.x * blockDim.x + threadIdx.x) >> 5;
    int lane  = threadIdx.x & 31;
    int half  = lane >> 4;
    int qlane = lane & 15;
    int seg   = warp * 2 + half;
    if (seg >= n_out) return;

    int cnt    = g_cursor[seg];
    int stored = cnt < CAP ? cnt : CAP;   // overflow handled post-pool
    const int* bins = g_bins + (size_t)seg * CAP;

    const float NI = -INFINITY;
    float4 acc = make_float4(NI, NI, NI, NI);

    int i = 0;
    for (; i + 1 < stored; i += 2) {
        int t0 = __ldg(&bins[i]);
        int t1 = __ldg(&bins[i + 1]);
        float4 a = __ldg(&feat4[(size_t)t0 * CV4 + qlane]);
        float4 b = __ldg(&feat4[(size_t)t1 * CV4 + qlane]);
        acc.x = fmaxf(acc.x, fmaxf(a.x, b.x));
        acc.y = fmaxf(acc.y, fmaxf(a.y, b.y));
        acc.z = fmaxf(acc.z, fmaxf(a.z, b.z));
        acc.w = fmaxf(acc.w, fmaxf(a.w, b.w));
    }
    if (i < stored) {
        int t0 = __ldg(&bins[i]);
        float4 a = __ldg(&feat4[(size_t)t0 * CV4 + qlane]);
        acc.x = fmaxf(acc.x, a.x);
        acc.y = fmaxf(acc.y, a.y);
        acc.z = fmaxf(acc.z, a.z);
        acc.w = fmaxf(acc.w, a.w);
    }

    if (cnt == 0) acc = make_float4(0.0f, 0.0f, 0.0f, 0.0f);
    __stcs(&out4[(size_t)seg * CV4 + qlane], acc);
}

// -------- kernel 4: resolve theoretical overflow (normally 0 entries) ------
__device__ __forceinline__ void atomicMaxFloat(float* addr, float val) {
    int* ia  = (int*)addr;
    int  old = *ia;
    while (__int_as_float(old) < val) {
        int assumed = old;
        old = atomicCAS(ia, assumed, __float_as_int(val));
        if (old == assumed) break;
    }
}

__global__ void k_overflow(const float* __restrict__ feat,
                           float* __restrict__ out, int n_out) {
    int n = g_ovf_cnt;
    if (n > OVF_CAP) n = OVF_CAP;
    if (n == 0) return;
    int warps = (gridDim.x * blockDim.x) >> 5;
    int w     = (blockIdx.x * blockDim.x + threadIdx.x) >> 5;
    int lane  = threadIdx.x & 31;
    for (int k = w; k < n; k += warps) {
        int2 e = g_ovf[k];
        if ((unsigned)e.x >= (unsigned)n_out) continue;
        const float* row = feat + (size_t)e.y * CCH;
        float*       dst = out  + (size_t)e.x * CCH;
        #pragma unroll
        for (int c = lane; c < CCH; c += 32)
            atomicMaxFloat(&dst[c], row[c]);
    }
}

// -------- optional tail: tuple's second element (feat_depth+1) --------
__global__ void k_tail(float* __restrict__ out, const int* __restrict__ feat_depth,
                       int begin, int total) {
    int i = begin + blockIdx.x * blockDim.x + threadIdx.x;
    if (i < total) out[i] = (float)(feat_depth[0] + 1);
}

extern "C" void kernel_launch(void* const* d_in, const int* in_sizes, int n_in,
                              void* d_out, int out_size) {
    const float* feat    = (const float*)d_in[0];
    const int*   src_ids = (const int*)  d_in[1];
    const int*   tgt_ids = (const int*)  d_in[2];
    const int*   ntypes  = (const int*)  d_in[3];

    int E  = in_sizes[1];
    int NT = (E > 0) ? in_sizes[3] / E : 3;
    if (E > MAX_E) E = MAX_E;
    if (NT < 1) NT = 1;

    int n_out = out_size / CCH;
    if (n_out > MAX_NOUT) n_out = MAX_NOUT;

    // 1. zero cursors
    k_zero<<<(n_out + 255) / 256, 256>>>(n_out);

    // 2. fused validity + direct scatter into fixed-capacity bins
    bool vec = (NT == 3) && (E % 4 == 0) &&
               ((((uintptr_t)src_ids | (uintptr_t)tgt_ids | (uintptr_t)ntypes) & 15u) == 0);
    if (vec) {
        int E4 = E / 4;
        k_scatter_v4<<<(E4 + 255) / 256, 256>>>((const int4*)src_ids,
                                                (const int4*)tgt_ids,
                                                (const int4*)ntypes, E4);
    } else {
        k_scatter_s<<<(E + 255) / 256, 256>>>(src_ids, tgt_ids, ntypes, E, NT);
    }

    // 3. pool: 2 segments per warp, 256 threads -> 16 segments per block
    int threads = 256;
    int segs_per_block = (threads / 32) * 2;
    int blocks = (n_out + segs_per_block - 1) / segs_per_block;
    k_pool<<<blocks, threads>>>((const float4*)feat, (float4*)d_out, n_out);

    // 4. resolve overflow entries (normally none; tiny fixed launch)
    k_overflow<<<8, 256>>>(feat, (float*)d_out, n_out);

    // tuple scalar tail (no-op for out_size == n_out*C)
    int main_elems = n_out * CCH;
    if (out_size > main_elems && n_in >= 6) {
        int extra = out_size - main_elems;
        k_tail<<<(extra + 255) / 256, 256>>>((float*)d_out, (const int*)d_in[5],
                                             main_elems, out_size);
    }
}

// round 10
// speedup vs baseline: 1.5941x; 1.0392x over previous
#include <cuda_runtime.h>
#include <math.h>
#include <stdint.h>

#define MAX_E     4194304
#define MAX_NOUT  524288
#define CCH       64            // channels
#define CV4       16            // float4 per row
#define CAP       16            // bin slots per segment (P(deg>16)~2e-4 -> overflow kernel)
#define OVF_CAP   262144

// -------- device scratch (no dynamic allocation allowed) --------
__device__ __align__(16) int g_bins[(size_t)MAX_NOUT * CAP];  // 32 MB
__device__ int  g_cursor[MAX_NOUT];      // per-segment valid-edge count
__device__ int  g_ovf_cnt;
__device__ int2 g_ovf[OVF_CAP];          // {seg, tgt} overflow edges

// -------- kernel 1: zero cursors --------
__global__ void k_zero(int n_out) {
    int i = blockIdx.x * blockDim.x + threadIdx.x;
    if (i < n_out) g_cursor[i] = 0;
    if (i == 0) g_ovf_cnt = 0;
}

// -------- kernel 2: fused validity + direct scatter (4 edges/thread) ------
__device__ __forceinline__ void scatter_one(int s, int tgt) {
    if ((unsigned)s >= (unsigned)MAX_NOUT) return;
    int p = atomicAdd(&g_cursor[s], 1);
    if (p < CAP) {
        g_bins[(size_t)s * CAP + p] = tgt;
    } else {
        int o = atomicAdd(&g_ovf_cnt, 1);
        if (o < OVF_CAP) g_ovf[o] = make_int2(s, tgt);
    }
}

__global__ void k_scatter_v4(const int4* __restrict__ src4,
                             const int4* __restrict__ tgt4,
                             const int4* __restrict__ nt4,
                             int E4) {
    int t = blockIdx.x * blockDim.x + threadIdx.x;
    if (t >= E4) return;
    int4 n0 = __ldg(&nt4[3 * t]);
    int4 n1 = __ldg(&nt4[3 * t + 1]);
    int4 n2 = __ldg(&nt4[3 * t + 2]);
    int4 s  = __ldg(&src4[t]);
    int4 tg = __ldg(&tgt4[t]);

    bool v0 = (n0.x >= 0) & (n0.y >= 0) & (n0.z >= 0);
    bool v1 = (n0.w >= 0) & (n1.x >= 0) & (n1.y >= 0);
    bool v2 = (n1.z >= 0) & (n1.w >= 0) & (n2.x >= 0);
    bool v3 = (n2.y >= 0) & (n2.z >= 0) & (n2.w >= 0);

    if (v0) scatter_one(s.x, tg.x);
    if (v1) scatter_one(s.y, tg.y);
    if (v2) scatter_one(s.z, tg.z);
    if (v3) scatter_one(s.w, tg.w);
}

// scalar fallback (odd shapes)
__global__ void k_scatter_s(const int* __restrict__ src_ids,
                            const int* __restrict__ tgt_ids,
                            const int* __restrict__ ntypes,
                            int E, int NT) {
    int e = blockIdx.x * blockDim.x + threadIdx.x;
    if (e >= E) return;
    const int* nt = ntypes + (size_t)e * NT;
    bool valid = true;
    for (int j = 0; j < NT; j++) valid &= (nt[j] >= 0);
    if (valid) scatter_one(src_ids[e], tgt_ids[e]);
}

// -------- kernel 3: pool. One segment per HALF-warp (2 segments/warp). ----
// 16 lanes x float4 cover the 64-ch row; up to 4 rows in flight per
// half-warp. bins/cursor read with .cs (read-once, evict-first) and output
// written with .cs so the streaming data never displaces feat rows in L2.
__global__ void k_pool(const float4* __restrict__ feat4,
                       float4* __restrict__ out4,
                       int n_out) {
    int warp  = (blockIdx.x * blockDim.x + threadIdx.x) >> 5;
    int lane  = threadIdx.x & 31;
    int half  = lane >> 4;
    int qlane = lane & 15;
    int seg   = warp * 2 + half;
    if (seg >= n_out) return;

    int cnt    = __ldcs(&g_cursor[seg]);
    int stored = cnt < CAP ? cnt : CAP;   // overflow handled post-pool
    const int* bins = g_bins + (size_t)seg * CAP;

    const float NI = -INFINITY;
    float4 acc = make_float4(NI, NI, NI, NI);

    int i = 0;
    for (; i + 3 < stored; i += 4) {
        int t0 = __ldcs(&bins[i]);
        int t1 = __ldcs(&bins[i + 1]);
        int t2 = __ldcs(&bins[i + 2]);
        int t3 = __ldcs(&bins[i + 3]);
        float4 a = __ldg(&feat4[(size_t)t0 * CV4 + qlane]);
        float4 b = __ldg(&feat4[(size_t)t1 * CV4 + qlane]);
        float4 c = __ldg(&feat4[(size_t)t2 * CV4 + qlane]);
        float4 d = __ldg(&feat4[(size_t)t3 * CV4 + qlane]);
        acc.x = fmaxf(fmaxf(fmaxf(acc.x, a.x), fmaxf(b.x, c.x)), d.x);
        acc.y = fmaxf(fmaxf(fmaxf(acc.y, a.y), fmaxf(b.y, c.y)), d.y);
        acc.z = fmaxf(fmaxf(fmaxf(acc.z, a.z), fmaxf(b.z, c.z)), d.z);
        acc.w = fmaxf(fmaxf(fmaxf(acc.w, a.w), fmaxf(b.w, c.w)), d.w);
    }
    for (; i + 1 < stored; i += 2) {
        int t0 = __ldcs(&bins[i]);
        int t1 = __ldcs(&bins[i + 1]);
        float4 a = __ldg(&feat4[(size_t)t0 * CV4 + qlane]);
        float4 b = __ldg(&feat4[(size_t)t1 * CV4 + qlane]);
        acc.x = fmaxf(acc.x, fmaxf(a.x, b.x));
        acc.y = fmaxf(acc.y, fmaxf(a.y, b.y));
        acc.z = fmaxf(acc.z, fmaxf(a.z, b.z));
        acc.w = fmaxf(acc.w, fmaxf(a.w, b.w));
    }
    if (i < stored) {
        int t0 = __ldcs(&bins[i]);
        float4 a = __ldg(&feat4[(size_t)t0 * CV4 + qlane]);
        acc.x = fmaxf(acc.x, a.x);
        acc.y = fmaxf(acc.y, a.y);
        acc.z = fmaxf(acc.z, a.z);
        acc.w = fmaxf(acc.w, a.w);
    }

    if (cnt == 0) acc = make_float4(0.0f, 0.0f, 0.0f, 0.0f);
    __stcs(&out4[(size_t)seg * CV4 + qlane], acc);
}

// -------- kernel 4: resolve overflow (few hundred entries at CAP=16) ------
__device__ __forceinline__ void atomicMaxFloat(float* addr, float val) {
    int* ia  = (int*)addr;
    int  old = *ia;
    while (__int_as_float(old) < val) {
        int assumed = old;
        old = atomicCAS(ia, assumed, __float_as_int(val));
        if (old == assumed) break;
    }
}

__global__ void k_overflow(const float* __restrict__ feat,
                           float* __restrict__ out, int n_out) {
    int n = g_ovf_cnt;
    if (n > OVF_CAP) n = OVF_CAP;
    if (n == 0) return;
    int warps = (gridDim.x * blockDim.x) >> 5;
    int w     = (blockIdx.x * blockDim.x + threadIdx.x) >> 5;
    int lane  = threadIdx.x & 31;
    for (int k = w; k < n; k += warps) {
        int2 e = g_ovf[k];
        if ((unsigned)e.x >= (unsigned)n_out) continue;
        const float* row = feat + (size_t)e.y * CCH;
        float*       dst = out  + (size_t)e.x * CCH;
        #pragma unroll
        for (int c = lane; c < CCH; c += 32)
            atomicMaxFloat(&dst[c], row[c]);
    }
}

// -------- optional tail: tuple's second element (feat_depth+1) --------
__global__ void k_tail(float* __restrict__ out, const int* __restrict__ feat_depth,
                       int begin, int total) {
    int i = begin + blockIdx.x * blockDim.x + threadIdx.x;
    if (i < total) out[i] = (float)(feat_depth[0] + 1);
}

extern "C" void kernel_launch(void* const* d_in, const int* in_sizes, int n_in,
                              void* d_out, int out_size) {
    const float* feat    = (const float*)d_in[0];
    const int*   src_ids = (const int*)  d_in[1];
    const int*   tgt_ids = (const int*)  d_in[2];
    const int*   ntypes  = (const int*)  d_in[3];

    int E  = in_sizes[1];
    int NT = (E > 0) ? in_sizes[3] / E : 3;
    if (E > MAX_E) E = MAX_E;
    if (NT < 1) NT = 1;

    int n_out = out_size / CCH;
    if (n_out > MAX_NOUT) n_out = MAX_NOUT;

    // 1. zero cursors
    k_zero<<<(n_out + 255) / 256, 256>>>(n_out);

    // 2. fused validity + direct scatter into fixed-capacity bins
    bool vec = (NT == 3) && (E % 4 == 0) &&
               ((((uintptr_t)src_ids | (uintptr_t)tgt_ids | (uintptr_t)ntypes) & 15u) == 0);
    if (vec) {
        int E4 = E / 4;
        k_scatter_v4<<<(E4 + 255) / 256, 256>>>((const int4*)src_ids,
                                                (const int4*)tgt_ids,
                                                (const int4*)ntypes, E4);
    } else {
        k_scatter_s<<<(E + 255) / 256, 256>>>(src_ids, tgt_ids, ntypes, E, NT);
    }

    // 3. pool: 2 segments per warp, 256 threads -> 16 segments per block
    int threads = 256;
    int segs_per_block = (threads / 32) * 2;
    int blocks = (n_out + segs_per_block - 1) / segs_per_block;
    k_pool<<<blocks, threads>>>((const float4*)feat, (float4*)d_out, n_out);

    // 4. resolve overflow entries (hundreds at CAP=16; warp per entry)
    k_overflow<<<32, 256>>>(feat, (float*)d_out, n_out);

    // tuple scalar tail (no-op for out_size == n_out*C)
    int main_elems = n_out * CCH;
    if (out_size > main_elems && n_in >= 6) {
        int extra = out_size - main_elems;
        k_tail<<<(extra + 255) / 256, 256>>>((float*)d_out, (const int*)d_in[5],
                                             main_elems, out_size);
    }
}

// round 12
// speedup vs baseline: 1.6441x; 1.0314x over previous
#include <cuda_runtime.h>
#include <math.h>
#include <stdint.h>

#define MAX_E     4194304
#define MAX_NOUT  524288
#define CCH       64            // channels
#define CV4       16            // float4 per row
#define CAP       16            // bin slots per segment (P(deg>16)~2e-4 -> overflow kernel)
#define OVF_CAP   262144

// -------- device scratch (no dynamic allocation allowed) --------
__device__ __align__(16) int g_bins[(size_t)MAX_NOUT * CAP];  // 32 MB
__device__ int  g_cursor[MAX_NOUT];      // per-segment valid-edge count
__device__ int  g_ovf_cnt;
__device__ int2 g_ovf[OVF_CAP];          // {seg, tgt} overflow edges

// -------- kernel 1: zero cursors --------
__global__ void k_zero(int n_out) {
    int i = blockIdx.x * blockDim.x + threadIdx.x;
    if (i < n_out) g_cursor[i] = 0;
    if (i == 0) g_ovf_cnt = 0;
}

// -------- kernel 2: fused validity + direct scatter (4 edges/thread) ------
// Stream inputs are read with .cs (read-once) so they do not evict the
// bins/cursor lines that k_pool reads right after this kernel.
__device__ __forceinline__ void scatter_one(int s, int tgt) {
    if ((unsigned)s >= (unsigned)MAX_NOUT) return;
    int p = atomicAdd(&g_cursor[s], 1);
    if (p < CAP) {
        g_bins[(size_t)s * CAP + p] = tgt;
    } else {
        int o = atomicAdd(&g_ovf_cnt, 1);
        if (o < OVF_CAP) g_ovf[o] = make_int2(s, tgt);
    }
}

__global__ void k_scatter_v4(const int4* __restrict__ src4,
                             const int4* __restrict__ tgt4,
                             const int4* __restrict__ nt4,
                             int E4) {
    int t = blockIdx.x * blockDim.x + threadIdx.x;
    if (t >= E4) return;
    int4 n0 = __ldcs(&nt4[3 * t]);
    int4 n1 = __ldcs(&nt4[3 * t + 1]);
    int4 n2 = __ldcs(&nt4[3 * t + 2]);
    int4 s  = __ldcs(&src4[t]);
    int4 tg = __ldcs(&tgt4[t]);

    bool v0 = (n0.x >= 0) & (n0.y >= 0) & (n0.z >= 0);
    bool v1 = (n0.w >= 0) & (n1.x >= 0) & (n1.y >= 0);
    bool v2 = (n1.z >= 0) & (n1.w >= 0) & (n2.x >= 0);
    bool v3 = (n2.y >= 0) & (n2.z >= 0) & (n2.w >= 0);

    if (v0) scatter_one(s.x, tg.x);
    if (v1) scatter_one(s.y, tg.y);
    if (v2) scatter_one(s.z, tg.z);
    if (v3) scatter_one(s.w, tg.w);
}

// scalar fallback (odd shapes)
__global__ void k_scatter_s(const int* __restrict__ src_ids,
                            const int* __restrict__ tgt_ids,
                            const int* __restrict__ ntypes,
                            int E, int NT) {
    int e = blockIdx.x * blockDim.x + threadIdx.x;
    if (e >= E) return;
    const int* nt = ntypes + (size_t)e * NT;
    bool valid = true;
    for (int j = 0; j < NT; j++) valid &= (nt[j] >= 0);
    if (valid) scatter_one(src_ids[e], tgt_ids[e]);
}

// -------- kernel 3: pool. One segment per HALF-warp (2 segments/warp). ----
// 16 lanes x float4 cover the 64-ch row. Up to 8 feat rows in flight per
// half-warp (deg>=8 tier), falling through to 4/2/1. bins reads default-
// cached (expected L2-resident from scatter); output written with .cs.
__global__ void k_pool(const float4* __restrict__ feat4,
                       float4* __restrict__ out4,
                       int n_out) {
    int warp  = (blockIdx.x * blockDim.x + threadIdx.x) >> 5;
    int lane  = threadIdx.x & 31;
    int half  = lane >> 4;
    int qlane = lane & 15;
    int seg   = warp * 2 + half;
    if (seg >= n_out) return;

    int cnt    = g_cursor[seg];
    int stored = cnt < CAP ? cnt : CAP;   // overflow handled post-pool
    const int* bins = g_bins + (size_t)seg * CAP;

    const float NI = -INFINITY;
    float4 acc = make_float4(NI, NI, NI, NI);

    int i = 0;
    for (; i + 7 < stored; i += 8) {
        int t0 = __ldg(&bins[i]);
        int t1 = __ldg(&bins[i + 1]);
        int t2 = __ldg(&bins[i + 2]);
        int t3 = __ldg(&bins[i + 3]);
        int t4 = __ldg(&bins[i + 4]);
        int t5 = __ldg(&bins[i + 5]);
        int t6 = __ldg(&bins[i + 6]);
        int t7 = __ldg(&bins[i + 7]);
        float4 a = __ldg(&feat4[(size_t)t0 * CV4 + qlane]);
        float4 b = __ldg(&feat4[(size_t)t1 * CV4 + qlane]);
        float4 c = __ldg(&feat4[(size_t)t2 * CV4 + qlane]);
        float4 d = __ldg(&feat4[(size_t)t3 * CV4 + qlane]);
        float4 e = __ldg(&feat4[(size_t)t4 * CV4 + qlane]);
        float4 f = __ldg(&feat4[(size_t)t5 * CV4 + qlane]);
        float4 g = __ldg(&feat4[(size_t)t6 * CV4 + qlane]);
        float4 h = __ldg(&feat4[(size_t)t7 * CV4 + qlane]);
        acc.x = fmaxf(acc.x, fmaxf(fmaxf(fmaxf(a.x, b.x), fmaxf(c.x, d.x)),
                                   fmaxf(fmaxf(e.x, f.x), fmaxf(g.x, h.x))));
        acc.y = fmaxf(acc.y, fmaxf(fmaxf(fmaxf(a.y, b.y), fmaxf(c.y, d.y)),
                                   fmaxf(fmaxf(e.y, f.y), fmaxf(g.y, h.y))));
        acc.z = fmaxf(acc.z, fmaxf(fmaxf(fmaxf(a.z, b.z), fmaxf(c.z, d.z)),
                                   fmaxf(fmaxf(e.z, f.z), fmaxf(g.z, h.z))));
        acc.w = fmaxf(acc.w, fmaxf(fmaxf(fmaxf(a.w, b.w), fmaxf(c.w, d.w)),
                                   fmaxf(fmaxf(e.w, f.w), fmaxf(g.w, h.w))));
    }
    for (; i + 3 < stored; i += 4) {
        int t0 = __ldg(&bins[i]);
        int t1 = __ldg(&bins[i + 1]);
        int t2 = __ldg(&bins[i + 2]);
        int t3 = __ldg(&bins[i + 3]);
        float4 a = __ldg(&feat4[(size_t)t0 * CV4 + qlane]);
        float4 b = __ldg(&feat4[(size_t)t1 * CV4 + qlane]);
        float4 c = __ldg(&feat4[(size_t)t2 * CV4 + qlane]);
        float4 d = __ldg(&feat4[(size_t)t3 * CV4 + qlane]);
        acc.x = fmaxf(fmaxf(fmaxf(acc.x, a.x), fmaxf(b.x, c.x)), d.x);
        acc.y = fmaxf(fmaxf(fmaxf(acc.y, a.y), fmaxf(b.y, c.y)), d.y);
        acc.z = fmaxf(fmaxf(fmaxf(acc.z, a.z), fmaxf(b.z, c.z)), d.z);
        acc.w = fmaxf(fmaxf(fmaxf(acc.w, a.w), fmaxf(b.w, c.w)), d.w);
    }
    for (; i + 1 < stored; i += 2) {
        int t0 = __ldg(&bins[i]);
        int t1 = __ldg(&bins[i + 1]);
        float4 a = __ldg(&feat4[(size_t)t0 * CV4 + qlane]);
        float4 b = __ldg(&feat4[(size_t)t1 * CV4 + qlane]);
        acc.x = fmaxf(acc.x, fmaxf(a.x, b.x));
        acc.y = fmaxf(acc.y, fmaxf(a.y, b.y));
        acc.z = fmaxf(acc.z, fmaxf(a.z, b.z));
        acc.w = fmaxf(acc.w, fmaxf(a.w, b.w));
    }
    if (i < stored) {
        int t0 = __ldg(&bins[i]);
        float4 a = __ldg(&feat4[(size_t)t0 * CV4 + qlane]);
        acc.x = fmaxf(acc.x, a.x);
        acc.y = fmaxf(acc.y, a.y);
        acc.z = fmaxf(acc.z, a.z);
        acc.w = fmaxf(acc.w, a.w);
    }

    if (cnt == 0) acc = make_float4(0.0f, 0.0f, 0.0f, 0.0f);
    __stcs(&out4[(size_t)seg * CV4 + qlane], acc);
}

// -------- kernel 4: resolve overflow (few hundred entries at CAP=16) ------
__device__ __forceinline__ void atomicMaxFloat(float* addr, float val) {
    int* ia  = (int*)addr;
    int  old = *ia;
    while (__int_as_float(old) < val) {
        int assumed = old;
        old = atomicCAS(ia, assumed, __float_as_int(val));
        if (old == assumed) break;
    }
}

__global__ void k_overflow(const float* __restrict__ feat,
                           float* __restrict__ out, int n_out) {
    int n = g_ovf_cnt;
    if (n > OVF_CAP) n = OVF_CAP;
    if (n == 0) return;
    int warps = (gridDim.x * blockDim.x) >> 5;
    int w     = (blockIdx.x * blockDim.x + threadIdx.x) >> 5;
    int lane  = threadIdx.x & 31;
    for (int k = w; k < n; k += warps) {
        int2 e = g_ovf[k];
        if ((unsigned)e.x >= (unsigned)n_out) continue;
        const float* row = feat + (size_t)e.y * CCH;
        float*       dst = out  + (size_t)e.x * CCH;
        #pragma unroll
        for (int c = lane; c < CCH; c += 32)
            atomicMaxFloat(&dst[c], row[c]);
    }
}

// -------- optional tail: tuple's second element (feat_depth+1) --------
__global__ void k_tail(float* __restrict__ out, const int* __restrict__ feat_depth,
                       int begin, int total) {
    int i = begin + blockIdx.x * blockDim.x + threadIdx.x;
    if (i < total) out[i] = (float)(feat_depth[0] + 1);
}

extern "C" void kernel_launch(void* const* d_in, const int* in_sizes, int n_in,
                              void* d_out, int out_size) {
    const float* feat    = (const float*)d_in[0];
    const int*   src_ids = (const int*)  d_in[1];
    const int*   tgt_ids = (const int*)  d_in[2];
    const int*   ntypes  = (const int*)  d_in[3];

    int E  = in_sizes[1];
    int NT = (E > 0) ? in_sizes[3] / E : 3;
    if (E > MAX_E) E = MAX_E;
    if (NT < 1) NT = 1;

    int n_out = out_size / CCH;
    if (n_out > MAX_NOUT) n_out = MAX_NOUT;

    // 1. zero cursors
    k_zero<<<(n_out + 255) / 256, 256>>>(n_out);

    // 2. fused validity + direct scatter into fixed-capacity bins
    bool vec = (NT == 3) && (E % 4 == 0) &&
               ((((uintptr_t)src_ids | (uintptr_t)tgt_ids | (uintptr_t)ntypes) & 15u) == 0);
    if (vec) {
        int E4 = E / 4;
        k_scatter_v4<<<(E4 + 255) / 256, 256>>>((const int4*)src_ids,
                                                (const int4*)tgt_ids,
                                                (const int4*)ntypes, E4);
    } else {
        k_scatter_s<<<(E + 255) / 256, 256>>>(src_ids, tgt_ids, ntypes, E, NT);
    }

    // 3. pool: 2 segments per warp, 256 threads -> 16 segments per block
    int threads = 256;
    int segs_per_block = (threads / 32) * 2;
    int blocks = (n_out + segs_per_block - 1) / segs_per_block;
    k_pool<<<blocks, threads>>>((const float4*)feat, (float4*)d_out, n_out);

    // 4. resolve overflow entries (hundreds at CAP=16; warp per entry)
    k_overflow<<<16, 256>>>(feat, (float*)d_out, n_out);

    // tuple scalar tail (no-op for out_size == n_out*C)
    int main_elems = n_out * CCH;
    if (out_size > main_elems && n_in >= 6) {
        int extra = out_size - main_elems;
        k_tail<<<(extra + 255) / 256, 256>>>((float*)d_out, (const int*)d_in[5],
                                             main_elems, out_size);
    }
}